// round 8
// baseline (speedup 1.0000x reference)
#include <cuda_runtime.h>
#include <cuda_bf16.h>
#include <math.h>
#include <stdint.h>

// Problem constants (fixed by setup_inputs)
#define NB      8
#define NA      16
#define NL      80
#define DIM     128
#define NH      6
#define HD      768
#define N_AGT   128
#define N_NODE  768
#define SPS     96
#define NQKV    2304          // 3 * HD
#define LN_EPS  1e-5f

// Scratch (device globals: no allocations allowed)
__device__ float g_QKV[N_NODE * NQKV];        // cols: [Q | K | V(relu)]
__device__ float g_part[NH * N_AGT * DIM];    // per-head partials of attO@Wout1

// ---------------------------------------------------------------------------
// Portable tensor-core helpers (mma.sync / ldmatrix — valid on compute_103)
// ---------------------------------------------------------------------------
__device__ __forceinline__ uint32_t smem_u32(const void* p) {
    uint32_t a;
    asm("{ .reg .u64 t; cvta.to.shared.u64 t, %1; cvt.u32.u64 %0, t; }"
        : "=r"(a) : "l"(p));
    return a;
}
__device__ __forceinline__ void ldsm4(uint32_t* r, uint32_t a) {
    asm volatile("ldmatrix.sync.aligned.m8n8.x4.shared.b16 {%0,%1,%2,%3}, [%4];"
                 : "=r"(r[0]), "=r"(r[1]), "=r"(r[2]), "=r"(r[3]) : "r"(a));
}
__device__ __forceinline__ void ldsm2t(uint32_t* r, uint32_t a) {
    asm volatile("ldmatrix.sync.aligned.m8n8.x2.trans.shared.b16 {%0,%1}, [%2];"
                 : "=r"(r[0]), "=r"(r[1]) : "r"(a));
}
__device__ __forceinline__ void mma_bf16(float* d, const uint32_t* a,
                                         const uint32_t* b) {
    asm volatile(
        "mma.sync.aligned.m16n8k16.row.col.f32.bf16.bf16.f32 "
        "{%0,%1,%2,%3}, {%4,%5,%6,%7}, {%8,%9}, {%0,%1,%2,%3};"
        : "+f"(d[0]), "+f"(d[1]), "+f"(d[2]), "+f"(d[3])
        : "r"(a[0]), "r"(a[1]), "r"(a[2]), "r"(a[3]), "r"(b[0]), "r"(b[1]));
}
// bf16 hi/lo split of two floats, packed as bf16x2 words
__device__ __forceinline__ void split2(float x, float y,
                                       uint32_t& hi, uint32_t& lo) {
    __nv_bfloat16 hx = __float2bfloat16_rn(x);
    __nv_bfloat16 hy = __float2bfloat16_rn(y);
    __nv_bfloat16 lx = __float2bfloat16_rn(x - __bfloat162float(hx));
    __nv_bfloat16 ly = __float2bfloat16_rn(y - __bfloat162float(hy));
    __nv_bfloat162 h = __halves2bfloat162(hx, hy);
    __nv_bfloat162 l = __halves2bfloat162(lx, ly);
    hi = *(uint32_t*)&h;
    lo = *(uint32_t*)&l;
}

// ---------------------------------------------------------------------------
// Kernel 1: bf16x3 tensor-core GEMM, conversion fused into the smem fill.
// Grid 78: bx<72 -> K/V tiles (row0 = (bx%6)*128, col0 = 768 + (bx/6)*128),
//          bx>=72 -> Q tiles (row0 = 0 [agents], col0 = (bx-72)*128).
// A in smem as [row][k] bf16 (hi/lo); B kept [k][n] and fragments loaded with
// ldmatrix.trans (row-major B pattern). 3 split-products accumulate in fp32.
// ---------------------------------------------------------------------------
#define ASTR   136
#define TB     (128 * ASTR * 2)
#define MMA_SMEM (4 * TB)

__global__ __launch_bounds__(256)
void qkv_mma(const float* __restrict__ agents,
             const float* __restrict__ lanes,
             const float* __restrict__ Wq,
             const float* __restrict__ Wk,
             const float* __restrict__ Wv)
{
    extern __shared__ char smem[];
    const uint32_t sb = smem_u32(smem);
    const int tid = threadIdx.x, wid = tid >> 5, lane = tid & 31;
    const int bx = blockIdx.x;
    int row0, col0;
    if (bx < 72) { row0 = (bx % 6) * 128; col0 = 768 + (bx / 6) * 128; }
    else         { row0 = 0;              col0 = (bx - 72) * 128;      }
    const float* __restrict__ W;
    int jl0;
    if (col0 < HD)          { W = Wq; jl0 = col0; }
    else if (col0 < 2 * HD) { W = Wk; jl0 = col0 - HD; }
    else                    { W = Wv; jl0 = col0 - 2 * HD; }

    char* Ahi = smem;
    char* Alo = smem + TB;
    char* Bhi = smem + 2 * TB;
    char* Blo = smem + 3 * TB;

    // Fill smem with on-the-fly fp32 -> bf16 hi/lo conversion.
    // A: [row r][k], B: [k][n] — both global reads fully coalesced.
    #pragma unroll
    for (int i = 0; i < 16; ++i) {
        int lin = tid + i * 256;             // 0..4095
        int q4 = (lin & 31) * 4;             // inner offset (k for A, n for B)
        int rk = lin >> 5;                   // 0..127 (row for A, k for B)
        uint32_t h0, l0, h1, l1;

        int grow = row0 + rk;
        const float* asrc = (grow < N_AGT) ? agents + grow * DIM
                                           : lanes + (grow - N_AGT) * DIM;
        float4 av = *(const float4*)(asrc + q4);
        split2(av.x, av.y, h0, l0);
        split2(av.z, av.w, h1, l1);
        *(uint2*)(Ahi + rk * (ASTR * 2) + q4 * 2) = make_uint2(h0, h1);
        *(uint2*)(Alo + rk * (ASTR * 2) + q4 * 2) = make_uint2(l0, l1);

        float4 bv = *(const float4*)(W + rk * HD + jl0 + q4);
        split2(bv.x, bv.y, h0, l0);
        split2(bv.z, bv.w, h1, l1);
        *(uint2*)(Bhi + rk * (ASTR * 2) + q4 * 2) = make_uint2(h0, h1);
        *(uint2*)(Blo + rk * (ASTR * 2) + q4 * 2) = make_uint2(l0, l1);
    }
    __syncthreads();

    const int wm = wid >> 2, wn = wid & 3;   // warp grid 2 x 4
    const int m0 = wm * 64, n0 = wn * 32;

    float acc[4][4][4] = {};

    const uint32_t a_off = (uint32_t)((m0 + (lane & 15)) * ASTR + (lane >> 4) * 8) * 2;
    const uint32_t b_off = (uint32_t)((lane & 15) * ASTR + n0) * 2;
    const uint32_t sA_hi = sb + a_off;
    const uint32_t sA_lo = sb + TB + a_off;
    const uint32_t sB_hi = sb + 2 * TB + b_off;
    const uint32_t sB_lo = sb + 3 * TB + b_off;

    #pragma unroll 1
    for (int ks = 0; ks < 8; ++ks) {
        const uint32_t kbA = (uint32_t)(ks * 32);              // A: k along cols
        const uint32_t kbB = (uint32_t)(ks * 16 * ASTR * 2);   // B: k along rows
        uint32_t ah[4][4], al[4][4], bh[4][2], bl[4][2];
        #pragma unroll
        for (int mt = 0; mt < 4; ++mt) {
            uint32_t moff = kbA + (uint32_t)(mt * 16 * ASTR * 2);
            ldsm4(ah[mt], sA_hi + moff);
            ldsm4(al[mt], sA_lo + moff);
        }
        #pragma unroll
        for (int nt = 0; nt < 4; ++nt) {
            uint32_t noff = kbB + (uint32_t)(nt * 16);         // nt*8 bf16 cols
            ldsm2t(bh[nt], sB_hi + noff);
            ldsm2t(bl[nt], sB_lo + noff);
        }
        #pragma unroll
        for (int mt = 0; mt < 4; ++mt)
            #pragma unroll
            for (int nt = 0; nt < 4; ++nt) {
                mma_bf16(acc[mt][nt], ah[mt], bh[nt]);
                mma_bf16(acc[mt][nt], ah[mt], bl[nt]);
                mma_bf16(acc[mt][nt], al[mt], bh[nt]);
            }
    }

    const bool dorelu = (col0 >= 2 * HD);
    const int rbase = row0 + m0 + (lane >> 2);
    const int cbase = col0 + n0 + (lane & 3) * 2;
    #pragma unroll
    for (int mt = 0; mt < 4; ++mt) {
        #pragma unroll
        for (int nt = 0; nt < 4; ++nt) {
            float2 v01 = make_float2(acc[mt][nt][0], acc[mt][nt][1]);
            float2 v23 = make_float2(acc[mt][nt][2], acc[mt][nt][3]);
            if (dorelu) {
                v01.x = fmaxf(v01.x, 0.f); v01.y = fmaxf(v01.y, 0.f);
                v23.x = fmaxf(v23.x, 0.f); v23.y = fmaxf(v23.y, 0.f);
            }
            int r = rbase + mt * 16;
            int c = cbase + nt * 8;
            *(float2*)(g_QKV + (size_t)r * NQKV + c) = v01;
            *(float2*)(g_QKV + (size_t)(r + 8) * NQKV + c) = v23;
        }
    }
}

// ---------------------------------------------------------------------------
// Kernel 2: fused attention + per-head Wout1 partial GEMM. 256 threads.
// ---------------------------------------------------------------------------
#define KP 132
#define SP 100
#define ATTN_SMEM ((SPS*KP + SPS*DIM + NA*KP + NA*SP) * 4)

__global__ __launch_bounds__(256)
void attn_kernel(const float* __restrict__ Wout1)
{
    const int b = blockIdx.x / NH;
    const int h = blockIdx.x % NH;
    extern __shared__ float sm[];
    float* Kt = sm;
    float* Vt = Kt + SPS * KP;
    float* Qs = Vt + SPS * DIM;
    float* S  = Qs + NA * KP;

    const int tid = threadIdx.x;

    #pragma unroll
    for (int i = 0; i < 12; ++i) {
        int lin = tid + i * 256;
        int j = lin >> 5, f = lin & 31;
        int g = (j < NA) ? (b * NA + j) : (N_AGT + b * NL + (j - NA));
        const float* base = g_QKV + (size_t)g * NQKV + h * DIM + f * 4;
        *(float4*)(Kt + j * KP + f * 4) = *(const float4*)(base + HD);
        *(float4*)(Vt + j * DIM + f * 4) = *(const float4*)(base + 2 * HD);
    }
    #pragma unroll
    for (int i = 0; i < 2; ++i) {
        int lin = tid + i * 256;
        int r = lin >> 5, f = lin & 31;
        *(float4*)(Qs + r * KP + f * 4) =
            *(const float4*)(g_QKV + (size_t)(b * NA + r) * NQKV + h * DIM + f * 4);
    }
    __syncthreads();

    const float scale = 0.08838834764831845f;
    if (tid < 192) {
        const int ti = tid / 48;
        const int tj = tid % 48;
        const int ib = ti * 4;
        float acc[4][2] = {};
        #pragma unroll 4
        for (int k = 0; k < DIM; k += 4) {
            float4 k0 = *(const float4*)(Kt + tj * KP + k);
            float4 k1 = *(const float4*)(Kt + (tj + 48) * KP + k);
            #pragma unroll
            for (int r = 0; r < 4; ++r) {
                float4 q = *(const float4*)(Qs + (ib + r) * KP + k);
                acc[r][0] += q.x * k0.x + q.y * k0.y + q.z * k0.z + q.w * k0.w;
                acc[r][1] += q.x * k1.x + q.y * k1.y + q.z * k1.z + q.w * k1.w;
            }
        }
        #pragma unroll
        for (int r = 0; r < 4; ++r) {
            S[(ib + r) * SP + tj]      = acc[r][0] * scale;
            S[(ib + r) * SP + tj + 48] = acc[r][1] * scale;
        }
    }
    __syncthreads();

    {
        const int w = tid >> 5, lane = tid & 31;
        #pragma unroll
        for (int rr = 0; rr < 2; ++rr) {
            const int i = w * 2 + rr;
            float v0 = S[i * SP + lane];
            float v1 = S[i * SP + lane + 32];
            float v2 = S[i * SP + lane + 64];
            float m = fmaxf(fmaxf(v0, v1), v2);
            #pragma unroll
            for (int off = 16; off > 0; off >>= 1)
                m = fmaxf(m, __shfl_xor_sync(0xffffffffu, m, off));
            float e0 = __expf(v0 - m), e1 = __expf(v1 - m), e2 = __expf(v2 - m);
            float s = e0 + e1 + e2;
            #pragma unroll
            for (int off = 16; off > 0; off >>= 1)
                s += __shfl_xor_sync(0xffffffffu, s, off);
            float rinv = 1.0f / s;
            S[i * SP + lane]      = e0 * rinv;
            S[i * SP + lane + 32] = e1 * rinv;
            S[i * SP + lane + 64] = e2 * rinv;
        }
    }
    __syncthreads();

    float* Ot = Qs;
    {
        const int dg = tid & 31;
        const int ig = tid >> 5;
        const int d = dg * 4;
        const int i0 = ig * 2;
        float4 a0 = make_float4(0.f, 0.f, 0.f, 0.f);
        float4 a1 = a0;
        #pragma unroll 4
        for (int k = 0; k < SPS; ++k) {
            float p0 = S[i0 * SP + k];
            float p1 = S[(i0 + 1) * SP + k];
            float4 v = *(const float4*)(Vt + k * DIM + d);
            a0.x += p0 * v.x; a0.y += p0 * v.y; a0.z += p0 * v.z; a0.w += p0 * v.w;
            a1.x += p1 * v.x; a1.y += p1 * v.y; a1.z += p1 * v.z; a1.w += p1 * v.w;
        }
        *(float4*)(Ot + i0 * DIM + d) = a0;
        *(float4*)(Ot + (i0 + 1) * DIM + d) = a1;
    }
    __syncthreads();

    // Partial P1 = Ot(16x128) @ Wout1[h*128 .. +128, :]  (k split in 2)
    {
        const int c = tid & 127;
        const int ks = tid >> 7;
        float acc[NA] = {};
        const float* Wb = Wout1 + (size_t)(h * DIM + ks * 64) * DIM + c;
        #pragma unroll 8
        for (int kk = 0; kk < 64; ++kk) {
            float w = Wb[kk * DIM];
            const float* o = Ot + ks * 64 + kk;
            #pragma unroll
            for (int r = 0; r < NA; ++r)
                acc[r] += o[r * DIM] * w;
        }
        float* red = Kt;
        if (ks == 1) {
            #pragma unroll
            for (int r = 0; r < NA; ++r) red[r * DIM + c] = acc[r];
        }
        __syncthreads();
        if (ks == 0) {
            float* dst = g_part + (size_t)h * N_AGT * DIM + (size_t)(b * NA) * DIM + c;
            #pragma unroll
            for (int r = 0; r < NA; ++r)
                dst[r * DIM] = acc[r] + red[r * DIM + c];
        }
    }
}

// ---------------------------------------------------------------------------
// Kernel 3: fused tail — 1 agent row per block, 512 threads, prefetched loads,
// warp-shuffle LayerNorm.
// ---------------------------------------------------------------------------
__global__ __launch_bounds__(512)
void tail_kernel(const float* __restrict__ agents,
                 const float* __restrict__ Wout2,
                 const float* __restrict__ W1,
                 const float* __restrict__ lng,
                 const float* __restrict__ lnb,
                 const float* __restrict__ W2,
                 float* __restrict__ out)
{
    const int r = blockIdx.x;
    const int tid = threadIdx.x;
    const int c = tid & 127;
    const int ks = tid >> 7;              // 0..3

    __shared__ float s_ar[DIM];
    __shared__ float s_t1[DIM];
    __shared__ float s_h[DIM];
    __shared__ float s_p[4][DIM];
    __shared__ float s_red[8];

    float wv2[32], wv1[32];
    {
        const float* w2b = Wout2 + (size_t)(ks * 32) * DIM + c;
        const float* w1b = W1 + (size_t)(ks * 32) * DIM + c;
        #pragma unroll
        for (int k = 0; k < 32; ++k) {
            wv2[k] = w2b[k * DIM];
            wv1[k] = w1b[k * DIM];
        }
    }
    float tp = 0.0f;
    if (ks < 3) {
        const float* gp = g_part + (size_t)(2 * ks) * N_AGT * DIM + (size_t)r * DIM + c;
        tp = gp[0] + gp[N_AGT * DIM];
    }
    const float ar = agents[r * DIM + c];
    const float g_c = lng[c], b_c = lnb[c];

    s_p[ks][c] = tp;
    __syncthreads();
    if (ks == 0) {
        s_t1[c] = fmaxf(s_p[0][c] + s_p[1][c] + s_p[2][c], 0.0f);
        s_ar[c] = ar;
    }
    __syncthreads();

    float pp = 0.0f;
    {
        const float* t1b = s_t1 + ks * 32;
        const float* arb = s_ar + ks * 32;
        #pragma unroll
        for (int k = 0; k < 32; ++k)
            pp += t1b[k] * wv2[k] + arb[k] * wv1[k];
    }
    s_p[ks][c] = pp;

    float wv3[32];
    {
        const float* w3b = W2 + (size_t)(ks * 32) * DIM + c;
        #pragma unroll
        for (int k = 0; k < 32; ++k) wv3[k] = w3b[k * DIM];
    }
    __syncthreads();

    const float pre = s_p[0][c] + s_p[1][c] + s_p[2][c] + s_p[3][c];

    if (ks == 0) {
        float s1 = pre, s2 = pre * pre;
        #pragma unroll
        for (int off = 16; off > 0; off >>= 1) {
            s1 += __shfl_xor_sync(0xffffffffu, s1, off);
            s2 += __shfl_xor_sync(0xffffffffu, s2, off);
        }
        if ((c & 31) == 0) {
            s_red[c >> 5] = s1;
            s_red[4 + (c >> 5)] = s2;
        }
    }
    __syncthreads();

    if (ks == 0) {
        float mu = (s_red[0] + s_red[1] + s_red[2] + s_red[3]) * (1.0f / 128.0f);
        float ex2 = (s_red[4] + s_red[5] + s_red[6] + s_red[7]) * (1.0f / 128.0f);
        float var = ex2 - mu * mu;
        float hn = (pre - mu) * rsqrtf(var + LN_EPS) * g_c + b_c;
        s_h[c] = fmaxf(hn, 0.0f);
    }
    __syncthreads();

    float op = 0.0f;
    {
        const float* hb = s_h + ks * 32;
        #pragma unroll
        for (int k = 0; k < 32; ++k) op += hb[k] * wv3[k];
    }
    s_p[ks][c] = op;
    __syncthreads();
    if (ks == 0) {
        float v = s_p[0][c] + s_p[1][c] + s_p[2][c] + s_p[3][c] + ar;
        out[r * DIM + c] = fmaxf(v, 0.0f);
    }
}

// ---------------------------------------------------------------------------
extern "C" void kernel_launch(void* const* d_in, const int* in_sizes, int n_in,
                              void* d_out, int out_size)
{
    const float* agents = (const float*)d_in[0];
    const float* lanes  = (const float*)d_in[1];
    const float* Wq     = (const float*)d_in[2];
    const float* Wk     = (const float*)d_in[3];
    const float* Wv     = (const float*)d_in[4];
    const float* Wout1  = (const float*)d_in[5];
    const float* Wout2  = (const float*)d_in[6];
    const float* W1     = (const float*)d_in[7];
    const float* lng    = (const float*)d_in[8];
    const float* lnb    = (const float*)d_in[9];
    const float* W2     = (const float*)d_in[10];
    (void)in_sizes; (void)n_in; (void)out_size;

    cudaFuncSetAttribute(qkv_mma,
                         cudaFuncAttributeMaxDynamicSharedMemorySize, MMA_SMEM);
    cudaFuncSetAttribute(attn_kernel,
                         cudaFuncAttributeMaxDynamicSharedMemorySize, ATTN_SMEM);

    qkv_mma<<<78, 256, MMA_SMEM>>>(agents, lanes, Wq, Wk, Wv);
    attn_kernel<<<NB * NH, 256, ATTN_SMEM>>>(Wout1);
    tail_kernel<<<N_AGT, 512>>>(agents, Wout2, W1, lng, lnb, W2,
                                (float*)d_out);
}

// round 9
// speedup vs baseline: 1.0012x; 1.0012x over previous
#include <cuda_runtime.h>
#include <cuda_bf16.h>
#include <math.h>
#include <stdint.h>

// Problem constants (fixed by setup_inputs)
#define NB      8
#define NA      16
#define NL      80
#define DIM     128
#define NH      6
#define HD      768
#define N_AGT   128
#define N_NODE  768
#define SPS     96
#define NQKV    2304          // 3 * HD
#define LN_EPS  1e-5f

// Scratch (device globals: no allocations allowed)
__device__ float g_QKV[N_NODE * NQKV];        // cols: [Q | K | V(relu)]
__device__ float g_part[NH * N_AGT * DIM];    // per-head partials of attO@Wout1

// ---------------------------------------------------------------------------
// Portable tensor-core helpers (mma.sync / ldmatrix — valid on compute_103)
// ---------------------------------------------------------------------------
__device__ __forceinline__ uint32_t smem_u32(const void* p) {
    uint32_t a;
    asm("{ .reg .u64 t; cvta.to.shared.u64 t, %1; cvt.u32.u64 %0, t; }"
        : "=r"(a) : "l"(p));
    return a;
}
__device__ __forceinline__ void ldsm4(uint32_t* r, uint32_t a) {
    asm volatile("ldmatrix.sync.aligned.m8n8.x4.shared.b16 {%0,%1,%2,%3}, [%4];"
                 : "=r"(r[0]), "=r"(r[1]), "=r"(r[2]), "=r"(r[3]) : "r"(a));
}
__device__ __forceinline__ void ldsm2t(uint32_t* r, uint32_t a) {
    asm volatile("ldmatrix.sync.aligned.m8n8.x2.trans.shared.b16 {%0,%1}, [%2];"
                 : "=r"(r[0]), "=r"(r[1]) : "r"(a));
}
__device__ __forceinline__ void mma_bf16(float* d, const uint32_t* a,
                                         const uint32_t* b) {
    asm volatile(
        "mma.sync.aligned.m16n8k16.row.col.f32.bf16.bf16.f32 "
        "{%0,%1,%2,%3}, {%4,%5,%6,%7}, {%8,%9}, {%0,%1,%2,%3};"
        : "+f"(d[0]), "+f"(d[1]), "+f"(d[2]), "+f"(d[3])
        : "r"(a[0]), "r"(a[1]), "r"(a[2]), "r"(a[3]), "r"(b[0]), "r"(b[1]));
}
// bf16 hi/lo split of two floats, packed as bf16x2 words
__device__ __forceinline__ void split2(float x, float y,
                                       uint32_t& hi, uint32_t& lo) {
    __nv_bfloat16 hx = __float2bfloat16_rn(x);
    __nv_bfloat16 hy = __float2bfloat16_rn(y);
    __nv_bfloat16 lx = __float2bfloat16_rn(x - __bfloat162float(hx));
    __nv_bfloat16 ly = __float2bfloat16_rn(y - __bfloat162float(hy));
    __nv_bfloat162 h = __halves2bfloat162(hx, hy);
    __nv_bfloat162 l = __halves2bfloat162(lx, ly);
    hi = *(uint32_t*)&h;
    lo = *(uint32_t*)&l;
}

// ---------------------------------------------------------------------------
// Kernel 1: bf16x3 tensor-core GEMM, conversion fused into the smem fill.
// 128x64 CTA tiles -> grid 156 (144 K/V + 12 Q), ~104KB smem -> 2 CTAs/SM.
// A in smem [row][k] bf16 hi/lo; B [k][n] with ldmatrix.trans fragments.
// ---------------------------------------------------------------------------
#define ASTR   136                       // A row stride (bf16)
#define BSTR   72                        // B row stride (bf16), 144B = 9*16
#define TA     (128 * ASTR * 2)          // 34816 B per A buffer
#define TBB    (128 * BSTR * 2)          // 18432 B per B buffer
#define MMA_SMEM (2 * TA + 2 * TBB)      // 106496 B

__global__ __launch_bounds__(256)
void qkv_mma(const float* __restrict__ agents,
             const float* __restrict__ lanes,
             const float* __restrict__ Wq,
             const float* __restrict__ Wk,
             const float* __restrict__ Wv)
{
    extern __shared__ char smem[];
    const uint32_t sb = smem_u32(smem);
    const int tid = threadIdx.x, wid = tid >> 5, lane = tid & 31;
    const int bx = blockIdx.x;
    int row0, col0;
    if (bx < 144) { row0 = (bx % 6) * 128; col0 = 768 + (bx / 6) * 64; }
    else          { row0 = 0;              col0 = (bx - 144) * 64;     }
    const float* __restrict__ W;
    int jl0;
    if (col0 < HD)          { W = Wq; jl0 = col0; }
    else if (col0 < 2 * HD) { W = Wk; jl0 = col0 - HD; }
    else                    { W = Wv; jl0 = col0 - 2 * HD; }

    char* Ahi = smem;
    char* Alo = smem + TA;
    char* Bhi = smem + 2 * TA;
    char* Blo = smem + 2 * TA + TBB;

    // ---- Fill A (128 rows x 128 k) with fp32->bf16 hi/lo conversion ----
    #pragma unroll
    for (int i = 0; i < 16; ++i) {
        int lin = tid + i * 256;             // 0..4095 float4s
        int q4 = (lin & 31) * 4;             // k offset
        int rk = lin >> 5;                   // row
        int grow = row0 + rk;
        const float* asrc = (grow < N_AGT) ? agents + grow * DIM
                                           : lanes + (grow - N_AGT) * DIM;
        float4 av = *(const float4*)(asrc + q4);
        uint32_t h0, l0, h1, l1;
        split2(av.x, av.y, h0, l0);
        split2(av.z, av.w, h1, l1);
        *(uint2*)(Ahi + rk * (ASTR * 2) + q4 * 2) = make_uint2(h0, h1);
        *(uint2*)(Alo + rk * (ASTR * 2) + q4 * 2) = make_uint2(l0, l1);
    }
    // ---- Fill B (128 k x 64 n) ----
    #pragma unroll
    for (int i = 0; i < 8; ++i) {
        int lin = tid + i * 256;             // 0..2047 float4s
        int n4 = (lin & 15) * 4;             // n offset
        int k = lin >> 4;                    // k row
        float4 bv = *(const float4*)(W + k * HD + jl0 + n4);
        uint32_t h0, l0, h1, l1;
        split2(bv.x, bv.y, h0, l0);
        split2(bv.z, bv.w, h1, l1);
        *(uint2*)(Bhi + k * (BSTR * 2) + n4 * 2) = make_uint2(h0, h1);
        *(uint2*)(Blo + k * (BSTR * 2) + n4 * 2) = make_uint2(l0, l1);
    }
    __syncthreads();

    // Warp grid 4m x 2n over (128 x 64): warp tile 32x32
    const int wm = wid >> 1, wn = wid & 1;
    const int m0 = wm * 32, n0 = wn * 32;

    float acc[2][4][4] = {};

    const uint32_t a_off = (uint32_t)((m0 + (lane & 15)) * ASTR + (lane >> 4) * 8) * 2;
    const uint32_t b_off = (uint32_t)((lane & 15) * BSTR + n0) * 2;
    const uint32_t sA_hi = sb + a_off;
    const uint32_t sA_lo = sb + TA + a_off;
    const uint32_t sB_hi = sb + 2 * TA + b_off;
    const uint32_t sB_lo = sb + 2 * TA + TBB + b_off;

    #pragma unroll 2
    for (int ks = 0; ks < 8; ++ks) {
        const uint32_t kbA = (uint32_t)(ks * 32);              // A: k along cols
        const uint32_t kbB = (uint32_t)(ks * 16 * BSTR * 2);   // B: k along rows
        uint32_t ah[2][4], al[2][4], bh[4][2], bl[4][2];
        #pragma unroll
        for (int mt = 0; mt < 2; ++mt) {
            uint32_t moff = kbA + (uint32_t)(mt * 16 * ASTR * 2);
            ldsm4(ah[mt], sA_hi + moff);
            ldsm4(al[mt], sA_lo + moff);
        }
        #pragma unroll
        for (int nt = 0; nt < 4; ++nt) {
            uint32_t noff = kbB + (uint32_t)(nt * 16);         // nt*8 bf16 cols
            ldsm2t(bh[nt], sB_hi + noff);
            ldsm2t(bl[nt], sB_lo + noff);
        }
        #pragma unroll
        for (int mt = 0; mt < 2; ++mt)
            #pragma unroll
            for (int nt = 0; nt < 4; ++nt) {
                mma_bf16(acc[mt][nt], ah[mt], bh[nt]);
                mma_bf16(acc[mt][nt], ah[mt], bl[nt]);
                mma_bf16(acc[mt][nt], al[mt], bh[nt]);
            }
    }

    const bool dorelu = (col0 >= 2 * HD);
    const int rbase = row0 + m0 + (lane >> 2);
    const int cbase = col0 + n0 + (lane & 3) * 2;
    #pragma unroll
    for (int mt = 0; mt < 2; ++mt) {
        #pragma unroll
        for (int nt = 0; nt < 4; ++nt) {
            float2 v01 = make_float2(acc[mt][nt][0], acc[mt][nt][1]);
            float2 v23 = make_float2(acc[mt][nt][2], acc[mt][nt][3]);
            if (dorelu) {
                v01.x = fmaxf(v01.x, 0.f); v01.y = fmaxf(v01.y, 0.f);
                v23.x = fmaxf(v23.x, 0.f); v23.y = fmaxf(v23.y, 0.f);
            }
            int r = rbase + mt * 16;
            int c = cbase + nt * 8;
            *(float2*)(g_QKV + (size_t)r * NQKV + c) = v01;
            *(float2*)(g_QKV + (size_t)(r + 8) * NQKV + c) = v23;
        }
    }
}

// ---------------------------------------------------------------------------
// Kernel 2: fused attention + per-head Wout1 partial GEMM. 256 threads.
// ---------------------------------------------------------------------------
#define KP 132
#define SP 100
#define ATTN_SMEM ((SPS*KP + SPS*DIM + NA*KP + NA*SP) * 4)

__global__ __launch_bounds__(256)
void attn_kernel(const float* __restrict__ Wout1)
{
    const int b = blockIdx.x / NH;
    const int h = blockIdx.x % NH;
    extern __shared__ float sm[];
    float* Kt = sm;
    float* Vt = Kt + SPS * KP;
    float* Qs = Vt + SPS * DIM;
    float* S  = Qs + NA * KP;

    const int tid = threadIdx.x;

    #pragma unroll
    for (int i = 0; i < 12; ++i) {
        int lin = tid + i * 256;
        int j = lin >> 5, f = lin & 31;
        int g = (j < NA) ? (b * NA + j) : (N_AGT + b * NL + (j - NA));
        const float* base = g_QKV + (size_t)g * NQKV + h * DIM + f * 4;
        *(float4*)(Kt + j * KP + f * 4) = *(const float4*)(base + HD);
        *(float4*)(Vt + j * DIM + f * 4) = *(const float4*)(base + 2 * HD);
    }
    #pragma unroll
    for (int i = 0; i < 2; ++i) {
        int lin = tid + i * 256;
        int r = lin >> 5, f = lin & 31;
        *(float4*)(Qs + r * KP + f * 4) =
            *(const float4*)(g_QKV + (size_t)(b * NA + r) * NQKV + h * DIM + f * 4);
    }
    __syncthreads();

    const float scale = 0.08838834764831845f;
    if (tid < 192) {
        const int ti = tid / 48;
        const int tj = tid % 48;
        const int ib = ti * 4;
        float acc[4][2] = {};
        #pragma unroll 4
        for (int k = 0; k < DIM; k += 4) {
            float4 k0 = *(const float4*)(Kt + tj * KP + k);
            float4 k1 = *(const float4*)(Kt + (tj + 48) * KP + k);
            #pragma unroll
            for (int r = 0; r < 4; ++r) {
                float4 q = *(const float4*)(Qs + (ib + r) * KP + k);
                acc[r][0] += q.x * k0.x + q.y * k0.y + q.z * k0.z + q.w * k0.w;
                acc[r][1] += q.x * k1.x + q.y * k1.y + q.z * k1.z + q.w * k1.w;
            }
        }
        #pragma unroll
        for (int r = 0; r < 4; ++r) {
            S[(ib + r) * SP + tj]      = acc[r][0] * scale;
            S[(ib + r) * SP + tj + 48] = acc[r][1] * scale;
        }
    }
    __syncthreads();

    {
        const int w = tid >> 5, lane = tid & 31;
        #pragma unroll
        for (int rr = 0; rr < 2; ++rr) {
            const int i = w * 2 + rr;
            float v0 = S[i * SP + lane];
            float v1 = S[i * SP + lane + 32];
            float v2 = S[i * SP + lane + 64];
            float m = fmaxf(fmaxf(v0, v1), v2);
            #pragma unroll
            for (int off = 16; off > 0; off >>= 1)
                m = fmaxf(m, __shfl_xor_sync(0xffffffffu, m, off));
            float e0 = __expf(v0 - m), e1 = __expf(v1 - m), e2 = __expf(v2 - m);
            float s = e0 + e1 + e2;
            #pragma unroll
            for (int off = 16; off > 0; off >>= 1)
                s += __shfl_xor_sync(0xffffffffu, s, off);
            float rinv = 1.0f / s;
            S[i * SP + lane]      = e0 * rinv;
            S[i * SP + lane + 32] = e1 * rinv;
            S[i * SP + lane + 64] = e2 * rinv;
        }
    }
    __syncthreads();

    float* Ot = Qs;
    {
        const int dg = tid & 31;
        const int ig = tid >> 5;
        const int d = dg * 4;
        const int i0 = ig * 2;
        float4 a0 = make_float4(0.f, 0.f, 0.f, 0.f);
        float4 a1 = a0;
        #pragma unroll 4
        for (int k = 0; k < SPS; ++k) {
            float p0 = S[i0 * SP + k];
            float p1 = S[(i0 + 1) * SP + k];
            float4 v = *(const float4*)(Vt + k * DIM + d);
            a0.x += p0 * v.x; a0.y += p0 * v.y; a0.z += p0 * v.z; a0.w += p0 * v.w;
            a1.x += p1 * v.x; a1.y += p1 * v.y; a1.z += p1 * v.z; a1.w += p1 * v.w;
        }
        *(float4*)(Ot + i0 * DIM + d) = a0;
        *(float4*)(Ot + (i0 + 1) * DIM + d) = a1;
    }
    __syncthreads();

    // Partial P1 = Ot(16x128) @ Wout1[h*128 .. +128, :]  (k split in 2)
    {
        const int c = tid & 127;
        const int ks = tid >> 7;
        float acc[NA] = {};
        const float* Wb = Wout1 + (size_t)(h * DIM + ks * 64) * DIM + c;
        #pragma unroll 8
        for (int kk = 0; kk < 64; ++kk) {
            float w = Wb[kk * DIM];
            const float* o = Ot + ks * 64 + kk;
            #pragma unroll
            for (int r = 0; r < NA; ++r)
                acc[r] += o[r * DIM] * w;
        }
        float* red = Kt;
        if (ks == 1) {
            #pragma unroll
            for (int r = 0; r < NA; ++r) red[r * DIM + c] = acc[r];
        }
        __syncthreads();
        if (ks == 0) {
            float* dst = g_part + (size_t)h * N_AGT * DIM + (size_t)(b * NA) * DIM + c;
            #pragma unroll
            for (int r = 0; r < NA; ++r)
                dst[r * DIM] = acc[r] + red[r * DIM + c];
        }
    }
}

// ---------------------------------------------------------------------------
// Kernel 3: fused tail — 1 agent row per block, 512 threads, prefetched loads,
// warp-shuffle LayerNorm.
// ---------------------------------------------------------------------------
__global__ __launch_bounds__(512)
void tail_kernel(const float* __restrict__ agents,
                 const float* __restrict__ Wout2,
                 const float* __restrict__ W1,
                 const float* __restrict__ lng,
                 const float* __restrict__ lnb,
                 const float* __restrict__ W2,
                 float* __restrict__ out)
{
    const int r = blockIdx.x;
    const int tid = threadIdx.x;
    const int c = tid & 127;
    const int ks = tid >> 7;              // 0..3

    __shared__ float s_ar[DIM];
    __shared__ float s_t1[DIM];
    __shared__ float s_h[DIM];
    __shared__ float s_p[4][DIM];
    __shared__ float s_red[8];

    float wv2[32], wv1[32];
    {
        const float* w2b = Wout2 + (size_t)(ks * 32) * DIM + c;
        const float* w1b = W1 + (size_t)(ks * 32) * DIM + c;
        #pragma unroll
        for (int k = 0; k < 32; ++k) {
            wv2[k] = w2b[k * DIM];
            wv1[k] = w1b[k * DIM];
        }
    }
    float tp = 0.0f;
    if (ks < 3) {
        const float* gp = g_part + (size_t)(2 * ks) * N_AGT * DIM + (size_t)r * DIM + c;
        tp = gp[0] + gp[N_AGT * DIM];
    }
    const float ar = agents[r * DIM + c];
    const float g_c = lng[c], b_c = lnb[c];

    s_p[ks][c] = tp;
    __syncthreads();
    if (ks == 0) {
        s_t1[c] = fmaxf(s_p[0][c] + s_p[1][c] + s_p[2][c], 0.0f);
        s_ar[c] = ar;
    }
    __syncthreads();

    float pp = 0.0f;
    {
        const float* t1b = s_t1 + ks * 32;
        const float* arb = s_ar + ks * 32;
        #pragma unroll
        for (int k = 0; k < 32; ++k)
            pp += t1b[k] * wv2[k] + arb[k] * wv1[k];
    }
    s_p[ks][c] = pp;

    float wv3[32];
    {
        const float* w3b = W2 + (size_t)(ks * 32) * DIM + c;
        #pragma unroll
        for (int k = 0; k < 32; ++k) wv3[k] = w3b[k * DIM];
    }
    __syncthreads();

    const float pre = s_p[0][c] + s_p[1][c] + s_p[2][c] + s_p[3][c];

    if (ks == 0) {
        float s1 = pre, s2 = pre * pre;
        #pragma unroll
        for (int off = 16; off > 0; off >>= 1) {
            s1 += __shfl_xor_sync(0xffffffffu, s1, off);
            s2 += __shfl_xor_sync(0xffffffffu, s2, off);
        }
        if ((c & 31) == 0) {
            s_red[c >> 5] = s1;
            s_red[4 + (c >> 5)] = s2;
        }
    }
    __syncthreads();

    if (ks == 0) {
        float mu = (s_red[0] + s_red[1] + s_red[2] + s_red[3]) * (1.0f / 128.0f);
        float ex2 = (s_red[4] + s_red[5] + s_red[6] + s_red[7]) * (1.0f / 128.0f);
        float var = ex2 - mu * mu;
        float hn = (pre - mu) * rsqrtf(var + LN_EPS) * g_c + b_c;
        s_h[c] = fmaxf(hn, 0.0f);
    }
    __syncthreads();

    float op = 0.0f;
    {
        const float* hb = s_h + ks * 32;
        #pragma unroll
        for (int k = 0; k < 32; ++k) op += hb[k] * wv3[k];
    }
    s_p[ks][c] = op;
    __syncthreads();
    if (ks == 0) {
        float v = s_p[0][c] + s_p[1][c] + s_p[2][c] + s_p[3][c] + ar;
        out[r * DIM + c] = fmaxf(v, 0.0f);
    }
}

// ---------------------------------------------------------------------------
extern "C" void kernel_launch(void* const* d_in, const int* in_sizes, int n_in,
                              void* d_out, int out_size)
{
    const float* agents = (const float*)d_in[0];
    const float* lanes  = (const float*)d_in[1];
    const float* Wq     = (const float*)d_in[2];
    const float* Wk     = (const float*)d_in[3];
    const float* Wv     = (const float*)d_in[4];
    const float* Wout1  = (const float*)d_in[5];
    const float* Wout2  = (const float*)d_in[6];
    const float* W1     = (const float*)d_in[7];
    const float* lng    = (const float*)d_in[8];
    const float* lnb    = (const float*)d_in[9];
    const float* W2     = (const float*)d_in[10];
    (void)in_sizes; (void)n_in; (void)out_size;

    cudaFuncSetAttribute(qkv_mma,
                         cudaFuncAttributeMaxDynamicSharedMemorySize, MMA_SMEM);
    cudaFuncSetAttribute(attn_kernel,
                         cudaFuncAttributeMaxDynamicSharedMemorySize, ATTN_SMEM);

    qkv_mma<<<156, 256, MMA_SMEM>>>(agents, lanes, Wq, Wk, Wv);
    attn_kernel<<<NB * NH, 256, ATTN_SMEM>>>(Wout1);
    tail_kernel<<<N_AGT, 512>>>(agents, Wout2, W1, lng, lnb, W2,
                                (float*)d_out);
}